// round 5
// baseline (speedup 1.0000x reference)
#include <cuda_runtime.h>
#include <cuda_bf16.h>
#include <math.h>

// Problem constants
#define NB   2048      // batch -> number of points
#define NT   128
#define NC   3
#define NJ   25
#define NE   64
#define NP   (NB - 1)  // 2047 deaths

// Scratch in device globals (no runtime allocation allowed)
__device__ float    g_buf[NB * NJ];            // pre-normalization norms g[b,k]
__device__ float    Dm_buf[(size_t)NB * NB];   // 16 MB distance matrix (L2 resident)
__device__ unsigned g_min_bits;
__device__ unsigned g_max_bits;

// ---------------------------------------------------------------------------
// Kernel 0: reset global min/max (runs every launch; graph-replayable)
// ---------------------------------------------------------------------------
__global__ void k_init() {
    g_min_bits = 0x7f800000u;  // +inf
    g_max_bits = 0u;           // g >= 0, so 0 is a valid max identity
}

// ---------------------------------------------------------------------------
// Kernel 1: a[b,j] = mean_{t,c} x[b,t,c,j];  g[b,k] = sqrt(sum_j (a_j-a_k)^2)
// Also global min/max of g via atomics on float bits (all values >= 0).
// One block per b, 256 threads.
// ---------------------------------------------------------------------------
__global__ void k_reduce(const float* __restrict__ x) {
    __shared__ float ap[8][NJ];   // partial sums per row-group
    __shared__ float a_s[NJ];

    const int b   = blockIdx.x;
    const int tid = threadIdx.x;
    const float* xb = x + (size_t)b * (NT * NC * NJ);   // 9600 floats, [384][25]

    // 256 threads -> 8 groups x 32 lanes (25 valid j per group)
    const int jj  = tid & 31;
    const int grp = tid >> 5;
    if (jj < NJ) {
        float s = 0.f;
        for (int r = grp; r < NT * NC; r += 8)
            s += xb[r * NJ + jj];
        ap[grp][jj] = s;
    }
    __syncthreads();

    if (tid < NJ) {
        float s = 0.f;
        #pragma unroll
        for (int g = 0; g < 8; ++g) s += ap[g][tid];
        a_s[tid] = s * (1.0f / (NT * NC));
    }
    __syncthreads();

    if (tid < 32) {
        float val = 0.f;
        if (tid < NJ) {
            float ak  = a_s[tid];
            float acc = 0.f;
            #pragma unroll
            for (int j = 0; j < NJ; ++j) {
                float d = a_s[j] - ak;
                acc = fmaf(d, d, acc);
            }
            val = sqrtf(acc);
            g_buf[b * NJ + tid] = val;
        }
        unsigned bmin = (tid < NJ) ? __float_as_uint(val) : 0x7f800000u;
        unsigned bmax = (tid < NJ) ? __float_as_uint(val) : 0u;
        unsigned wmin = __reduce_min_sync(0xffffffffu, bmin);
        unsigned wmax = __reduce_max_sync(0xffffffffu, bmax);
        if (tid == 0) {
            atomicMin(&g_min_bits, wmin);
            atomicMax(&g_max_bits, wmax);
        }
    }
}

// ---------------------------------------------------------------------------
// Kernel 2: Dm[i,k] = sqrt(max(sum_j (h_i - h_k)^2, 1e-12)),
// h = (g - lo)/(hi - lo) normalized on the fly.
// Tiled: grid (16,16), 256 threads, 128x128 tile, 8x8 outputs per thread.
// ---------------------------------------------------------------------------
__global__ void k_dist() {
    __shared__ float A[128][26];
    __shared__ float Bm[128][26];

    const int tid = threadIdx.x;
    const int r0  = blockIdx.y * 128;
    const int c0  = blockIdx.x * 128;

    const float lo  = __uint_as_float(g_min_bits);
    const float hi  = __uint_as_float(g_max_bits);
    const float rng = hi - lo;
    const float inv = (rng > 1e-8f) ? (1.0f / rng) : 0.0f;  // !safe -> h = 0

    for (int i = tid; i < 128 * NJ; i += 256) {
        int r = i / NJ, j = i - r * NJ;
        A[r][j]  = (g_buf[(r0 + r) * NJ + j] - lo) * inv;
        Bm[r][j] = (g_buf[(c0 + r) * NJ + j] - lo) * inv;
    }
    __syncthreads();

    const int tx = tid & 15;
    const int ty = tid >> 4;

    float acc[8][8];
    #pragma unroll
    for (int i = 0; i < 8; ++i)
        #pragma unroll
        for (int k = 0; k < 8; ++k) acc[i][k] = 0.f;

    #pragma unroll
    for (int j = 0; j < NJ; ++j) {
        float ra[8], rb[8];
        #pragma unroll
        for (int i = 0; i < 8; ++i) {
            ra[i] = A[ty + 16 * i][j];
            rb[i] = Bm[tx + 16 * i][j];
        }
        #pragma unroll
        for (int i = 0; i < 8; ++i)
            #pragma unroll
            for (int k = 0; k < 8; ++k) {
                float d = ra[i] - rb[k];
                acc[i][k] = fmaf(d, d, acc[i][k]);
            }
    }

    #pragma unroll
    for (int i = 0; i < 8; ++i) {
        int rr = r0 + ty + 16 * i;
        #pragma unroll
        for (int k = 0; k < 8; ++k) {
            int cc = c0 + tx + 16 * k;
            Dm_buf[(size_t)rr * NB + cc] = sqrtf(fmaxf(acc[i][k], 1e-12f));
        }
    }
}

// ---------------------------------------------------------------------------
// Kernel 3: Prim's MST (exact replica of reference semantics, incl. argmin
// lowest-index tie break) + fused StructureElement layer.
// Single block, 512 threads, 4 entries per thread (mind in registers).
// One __syncthreads per iteration (reduction slots double-buffered).
// ---------------------------------------------------------------------------
__global__ void __launch_bounds__(512, 1)
k_prim(const float* __restrict__ centres,
       const float* __restrict__ sharp,
       float* __restrict__ out) {
    __shared__ float    deaths_s[NP];
    __shared__ unsigned red_v[2][16];
    __shared__ int      red_i[2][16];
    __shared__ float    out_s[NE];

    const int tid  = threadIdx.x;
    const int lane = tid & 31;
    const int warp = tid >> 5;
    const unsigned INFB = 0x7f800000u;

    if (tid < NE) out_s[tid] = 0.f;

    // init: mind = Dm[0][:], node 0 in tree
    const float4* row0 = (const float4*)Dm_buf;
    float4 r0 = row0[tid];
    float m0 = r0.x, m1 = r0.y, m2 = r0.z, m3 = r0.w;
    unsigned alive = (tid == 0) ? 0xEu : 0xFu;

    for (int it = 0; it < NP; ++it) {
        const int buf = it & 1;

        // masked candidates (exact f32 bits; >=0 so uint order == float order)
        unsigned v0 = (alive & 1u) ? __float_as_uint(m0) : INFB;
        unsigned v1 = (alive & 2u) ? __float_as_uint(m1) : INFB;
        unsigned v2 = (alive & 4u) ? __float_as_uint(m2) : INFB;
        unsigned v3 = (alive & 8u) ? __float_as_uint(m3) : INFB;

        // local argmin of 4 (strict < keeps lowest index on ties)
        unsigned b01 = v0; int i01 = 0;
        if (v1 < b01) { b01 = v1; i01 = 1; }
        unsigned b23 = v2; int i23 = 2;
        if (v3 < b23) { b23 = v3; i23 = 3; }
        unsigned bb = b01; int ii = i01;
        if (b23 < bb) { bb = b23; ii = i23; }
        int idx = tid * 4 + ii;

        // warp argmin: exact value REDUX + lowest-lane match
        unsigned wmin = __reduce_min_sync(0xffffffffu, bb);
        unsigned ball = __ballot_sync(0xffffffffu, bb == wmin);
        int src  = __ffs(ball) - 1;
        int widx = __shfl_sync(0xffffffffu, idx, src);
        if (lane == 0) { red_v[buf][warp] = wmin; red_i[buf][warp] = widx; }
        __syncthreads();

        // block argmin: every warp reduces the 16 warp winners redundantly
        // (removes the second barrier; slots are double-buffered)
        unsigned vv = (lane < 16) ? red_v[buf][lane] : INFB;
        int      iv = (lane < 16) ? red_i[buf][lane] : 0;
        unsigned gmin = __reduce_min_sync(0xffffffffu, vv);
        unsigned b2   = __ballot_sync(0xffffffffu, vv == gmin);
        int s2 = __ffs(b2) - 1;
        int j  = __shfl_sync(0xffffffffu, iv, s2);

        // issue the row load as early as possible (longest-latency op on the
        // serial chain), then do the cheap bookkeeping while it's in flight
        const float4* rp = (const float4*)(Dm_buf + (size_t)j * NB);
        float4 rr = rp[tid];

        if (tid == 0) deaths_s[it] = __uint_as_float(gmin);
        if ((j >> 2) == tid) alive &= ~(1u << (j & 3));

        m0 = fminf(m0, rr.x);
        m1 = fminf(m1, rr.y);
        m2 = fminf(m2, rr.z);
        m3 = fminf(m3, rr.w);
    }
    __syncthreads();

    // StructureElementLayer: out[e] = sum_p exp(-(sx^2*cx^2 + sy^2*(w-cy)^2))
    const int e  = tid & 63;
    const float cx = centres[2 * e],  cy = centres[2 * e + 1];
    const float sx = sharp[2 * e],    sy = sharp[2 * e + 1];
    const float t0  = sx * sx * cx * cx;
    const float s2y = sy * sy;
    float acc = 0.f;
    for (int p = tid >> 6; p < NP; p += 8) {
        float d = deaths_s[p] - cy;
        acc += expf(-(t0 + s2y * d * d));
    }
    atomicAdd(&out_s[e], acc);
    __syncthreads();
    if (tid < NE) out[tid] = out_s[tid];
}

// ---------------------------------------------------------------------------
extern "C" void kernel_launch(void* const* d_in, const int* in_sizes, int n_in,
                              void* d_out, int out_size) {
    const float* x       = (const float*)d_in[0];
    const float* centres = (const float*)d_in[1];
    const float* sharp   = (const float*)d_in[2];
    float*       out     = (float*)d_out;

    k_init<<<1, 1>>>();
    k_reduce<<<NB, 256>>>(x);
    k_dist<<<dim3(16, 16), 256>>>();
    k_prim<<<1, 512>>>(centres, sharp, out);
}

// round 6
// speedup vs baseline: 6.9188x; 6.9188x over previous
#include <cuda_runtime.h>
#include <cuda_bf16.h>
#include <math.h>

// Problem constants
#define NB   2048      // batch -> number of points
#define NT   128
#define NC   3
#define NJ   25
#define NE   64
#define NP   (NB - 1)  // 2047 deaths

#define GRID_BVK   148
#define THR_BVK    1024
#define ROUNDS     12

// Scratch in device globals (no runtime allocation allowed)
__device__ float    g_buf[NB * NJ];
__device__ float    Dm_buf[(size_t)NB * NB];   // 16 MB distance matrix (L2 resident)
__device__ unsigned g_min_bits;
__device__ unsigned g_max_bits;

// Boruvka state
__device__ unsigned long long best_comp[NB];
__device__ int   comp_arr[NB];
__device__ int   parent_arr[NB];
__device__ float deaths_g[NB];                 // slot = hooking root; -1 = unused
__device__ volatile int      n_comp;
__device__ unsigned          bar_count;
__device__ volatile unsigned bar_gen;

// ---------------------------------------------------------------------------
__global__ void k_init() {
    g_min_bits = 0x7f800000u;
    g_max_bits = 0u;
    bar_count  = 0;
    bar_gen    = 0;
    n_comp     = NB;
}

// ---------------------------------------------------------------------------
// Kernel 1: a[b,j] = mean_{t,c} x[b,t,c,j];  g[b,k] = sqrt(sum_j (a_j-a_k)^2)
// ---------------------------------------------------------------------------
__global__ void k_reduce(const float* __restrict__ x) {
    __shared__ float ap[8][NJ];
    __shared__ float a_s[NJ];

    const int b   = blockIdx.x;
    const int tid = threadIdx.x;
    const float* xb = x + (size_t)b * (NT * NC * NJ);

    const int jj  = tid & 31;
    const int grp = tid >> 5;
    if (jj < NJ) {
        float s = 0.f;
        for (int r = grp; r < NT * NC; r += 8)
            s += xb[r * NJ + jj];
        ap[grp][jj] = s;
    }
    __syncthreads();

    if (tid < NJ) {
        float s = 0.f;
        #pragma unroll
        for (int g = 0; g < 8; ++g) s += ap[g][tid];
        a_s[tid] = s * (1.0f / (NT * NC));
    }
    __syncthreads();

    if (tid < 32) {
        float val = 0.f;
        if (tid < NJ) {
            float ak  = a_s[tid];
            float acc = 0.f;
            #pragma unroll
            for (int j = 0; j < NJ; ++j) {
                float d = a_s[j] - ak;
                acc = fmaf(d, d, acc);
            }
            val = sqrtf(acc);
            g_buf[b * NJ + tid] = val;
        }
        unsigned bmin = (tid < NJ) ? __float_as_uint(val) : 0x7f800000u;
        unsigned bmax = (tid < NJ) ? __float_as_uint(val) : 0u;
        unsigned wmin = __reduce_min_sync(0xffffffffu, bmin);
        unsigned wmax = __reduce_max_sync(0xffffffffu, bmax);
        if (tid == 0) {
            atomicMin(&g_min_bits, wmin);
            atomicMax(&g_max_bits, wmax);
        }
    }
}

// ---------------------------------------------------------------------------
// Kernel 2: Dm[i,k] = sqrt(max(||h_i - h_k||^2, 1e-12)), h normalized on the fly
// ---------------------------------------------------------------------------
__global__ void k_dist() {
    __shared__ float A[128][26];
    __shared__ float Bm[128][26];

    const int tid = threadIdx.x;
    const int r0  = blockIdx.y * 128;
    const int c0  = blockIdx.x * 128;

    const float lo  = __uint_as_float(g_min_bits);
    const float hi  = __uint_as_float(g_max_bits);
    const float rng = hi - lo;
    const float inv = (rng > 1e-8f) ? (1.0f / rng) : 0.0f;

    for (int i = tid; i < 128 * NJ; i += 256) {
        int r = i / NJ, j = i - r * NJ;
        A[r][j]  = (g_buf[(r0 + r) * NJ + j] - lo) * inv;
        Bm[r][j] = (g_buf[(c0 + r) * NJ + j] - lo) * inv;
    }
    __syncthreads();

    const int tx = tid & 15;
    const int ty = tid >> 4;

    float acc[8][8];
    #pragma unroll
    for (int i = 0; i < 8; ++i)
        #pragma unroll
        for (int k = 0; k < 8; ++k) acc[i][k] = 0.f;

    #pragma unroll
    for (int j = 0; j < NJ; ++j) {
        float ra[8], rb[8];
        #pragma unroll
        for (int i = 0; i < 8; ++i) {
            ra[i] = A[ty + 16 * i][j];
            rb[i] = Bm[tx + 16 * i][j];
        }
        #pragma unroll
        for (int i = 0; i < 8; ++i)
            #pragma unroll
            for (int k = 0; k < 8; ++k) {
                float d = ra[i] - rb[k];
                acc[i][k] = fmaf(d, d, acc[i][k]);
            }
    }

    #pragma unroll
    for (int i = 0; i < 8; ++i) {
        int rr = r0 + ty + 16 * i;
        #pragma unroll
        for (int k = 0; k < 8; ++k) {
            int cc = c0 + tx + 16 * k;
            Dm_buf[(size_t)rr * NB + cc] = sqrtf(fmaxf(acc[i][k], 1e-12f));
        }
    }
}

// ---------------------------------------------------------------------------
// Grid-wide sense-reversing barrier (all GRID_BVK blocks co-resident).
// ---------------------------------------------------------------------------
__device__ __forceinline__ void grid_barrier() {
    __syncthreads();
    if (threadIdx.x == 0) {
        __threadfence();                 // release
        unsigned gen = bar_gen;          // read BEFORE arriving
        if (atomicAdd(&bar_count, 1u) == (unsigned)(gridDim.x - 1)) {
            bar_count = 0;
            __threadfence();
            bar_gen = gen + 1;
        } else {
            while (bar_gen == gen) { }
        }
        __threadfence();                 // acquire
    }
    __syncthreads();
}

// ---------------------------------------------------------------------------
// Kernel 3: persistent parallel Boruvka over Dm.
// key = (w_bits<<22) | (i<<11) | j   (w >= 0 so uint order == float order)
// ---------------------------------------------------------------------------
__global__ void __launch_bounds__(THR_BVK, 1)
k_boruvka() {
    const int tg   = blockIdx.x * THR_BVK + threadIdx.x;  // 0 .. 151551
    const int lane = threadIdx.x & 31;
    const unsigned long long KMAX = 0xFFFFFFFFFFFFFFFFull;

    // init state (every launch; graph-replayable)
    if (tg < NB) {
        comp_arr[tg]   = tg;
        parent_arr[tg] = tg;
        best_comp[tg]  = KMAX;
        deaths_g[tg]   = -1.0f;
    }
    grid_barrier();

    const int gw   = tg >> 5;          // global warp id, 0..4735
    const int i    = gw & (NB - 1);    // point handled by this warp
    const int part = gw >> 11;         // 0/1 = row half, 2 = idle

    for (int round = 0; round < ROUNDS; ++round) {
        const int nc = n_comp;         // volatile; fenced by barrier

        // ---- phase A: per-point min cross-component edge ----
        if (nc > 1 && part < 2) {
            const int ci = comp_arr[i];
            const float4* row = (const float4*)(Dm_buf + (size_t)i * NB + part * 1024);
            const int4*   cp  = (const int4*)(comp_arr + part * 1024);
            unsigned long long best = KMAX;
            const unsigned long long ibits = (unsigned long long)(i << 11);

            #pragma unroll
            for (int k = 0; k < 8; ++k) {
                const int v = k * 32 + lane;
                float4 w  = row[v];
                int4   c4 = cp[v];
                const int jb = part * 1024 + v * 4;
                if (c4.x != ci) {
                    unsigned long long key = ((unsigned long long)__float_as_uint(w.x) << 22) | ibits | (jb + 0);
                    if (key < best) best = key;
                }
                if (c4.y != ci) {
                    unsigned long long key = ((unsigned long long)__float_as_uint(w.y) << 22) | ibits | (jb + 1);
                    if (key < best) best = key;
                }
                if (c4.z != ci) {
                    unsigned long long key = ((unsigned long long)__float_as_uint(w.z) << 22) | ibits | (jb + 2);
                    if (key < best) best = key;
                }
                if (c4.w != ci) {
                    unsigned long long key = ((unsigned long long)__float_as_uint(w.w) << 22) | ibits | (jb + 3);
                    if (key < best) best = key;
                }
            }
            #pragma unroll
            for (int off = 16; off; off >>= 1) {
                unsigned long long o = __shfl_down_sync(0xffffffffu, best, off);
                if (o < best) best = o;
            }
            if (lane == 0 && best != KMAX)
                atomicMin(&best_comp[ci], best);
        }
        grid_barrier();

        // ---- phase B: hook roots along min outgoing edge ----
        if (nc > 1 && tg < NB) {
            const int c = tg;
            if (comp_arr[c] == c) {
                unsigned long long b = best_comp[c];
                if (b != KMAX) {
                    const int j  = (int)(b & 2047u);
                    const int rj = comp_arr[j];
                    // mutual-pair detection: does rj's best point back at c?
                    unsigned long long b2 = best_comp[rj];
                    int back = -1;
                    if (b2 != KMAX) back = comp_arr[(int)(b2 & 2047u)];
                    const bool skip = (back == c) && (c > rj);
                    if (!skip) {
                        parent_arr[c] = rj;
                        deaths_g[c]   = __uint_as_float((unsigned)(b >> 22));
                        atomicSub((int*)&n_comp, 1);
                    }
                }
            }
        }
        grid_barrier();

        // ---- phase C: flatten labels, reset per-round state ----
        if (tg < NB) {
            int r = comp_arr[tg];
            while (parent_arr[r] != r) r = parent_arr[r];
            comp_arr[tg]   = r;
            parent_arr[tg] = r;        // path compression
            best_comp[tg]  = KMAX;
        }
        grid_barrier();
    }
}

// ---------------------------------------------------------------------------
// Kernel 4: StructureElementLayer over the 2047 deaths (fixed-order sum).
// out[e] = sum_p exp(-(sx^2*cx^2 + sy^2*(w-cy)^2))
// ---------------------------------------------------------------------------
__global__ void __launch_bounds__(512, 1)
k_post(const float* __restrict__ centres,
       const float* __restrict__ sharp,
       float* __restrict__ out) {
    __shared__ float part_s[8][NE];

    const int tid = threadIdx.x;
    const int e   = tid & 63;
    const int g   = tid >> 6;          // 0..7

    const float cx = centres[2 * e],  cy = centres[2 * e + 1];
    const float sx = sharp[2 * e],    sy = sharp[2 * e + 1];
    const float t0  = sx * sx * cx * cx;
    const float s2y = sy * sy;

    float acc = 0.f;
    for (int c = g; c < NB; c += 8) {
        float d = deaths_g[c];
        if (d >= 0.f) {
            float dd = d - cy;
            acc += expf(-(t0 + s2y * dd * dd));
        }
    }
    part_s[g][e] = acc;
    __syncthreads();

    if (tid < NE) {
        float s = 0.f;
        #pragma unroll
        for (int k = 0; k < 8; ++k) s += part_s[k][tid];
        out[tid] = s;
    }
}

// ---------------------------------------------------------------------------
extern "C" void kernel_launch(void* const* d_in, const int* in_sizes, int n_in,
                              void* d_out, int out_size) {
    const float* x       = (const float*)d_in[0];
    const float* centres = (const float*)d_in[1];
    const float* sharp   = (const float*)d_in[2];
    float*       out     = (float*)d_out;

    k_init<<<1, 1>>>();
    k_reduce<<<NB, 256>>>(x);
    k_dist<<<dim3(16, 16), 256>>>();
    k_boruvka<<<GRID_BVK, THR_BVK>>>();
    k_post<<<1, 512>>>(centres, sharp, out);
}

// round 7
// speedup vs baseline: 14.5265x; 2.0996x over previous
#include <cuda_runtime.h>
#include <cuda_bf16.h>
#include <math.h>

// Problem constants
#define NB   2048      // batch -> number of points
#define NT   128
#define NC   3
#define NJ   25
#define NE   64
#define NP   (NB - 1)

#define GRID_BVK   128          // 4096 warps = 2048 points x 2 half-rows
#define THR_BVK    1024
#define ROUNDS     12           // >= ceil(log2(2048)) + 1 safety

#define SMEM_BVK   (32 * 1024 * 4 + NB * 4)   // dm slice 128KB + comp 8KB

// Scratch in device globals (no runtime allocation allowed)
__device__ float    g_buf[NB * NJ];
__device__ float    Dm_buf[(size_t)NB * NB];   // 16 MB distance matrix
__device__ unsigned g_min_bits;
__device__ unsigned g_max_bits;

// Boruvka state
__device__ unsigned long long best_r[ROUNDS][NB];  // fresh buffer per round
__device__ int   parent_arr[NB];
__device__ float deaths_g[NB];                     // slot = hooking root; -1 unused
__device__ volatile int      n_comp;
__device__ unsigned          bar_count;
__device__ volatile unsigned bar_gen;

// ---------------------------------------------------------------------------
// Kernel 0: init all state (grid 96x256 = 24576 threads = ROUNDS*NB)
// ---------------------------------------------------------------------------
__global__ void k_init() {
    const int idx = blockIdx.x * 256 + threadIdx.x;
    ((unsigned long long*)best_r)[idx] = 0xFFFFFFFFFFFFFFFFull;
    if (idx < NB) {
        parent_arr[idx] = idx;
        deaths_g[idx]   = -1.0f;
    }
    if (idx == 0) {
        g_min_bits = 0x7f800000u;
        g_max_bits = 0u;
        bar_count  = 0;
        bar_gen    = 0;
        n_comp     = NB;
    }
}

// ---------------------------------------------------------------------------
// Kernel 1: a[b,j] = mean_{t,c} x[b,t,c,j];  g[b,k] = sqrt(sum_j (a_j-a_k)^2)
// ---------------------------------------------------------------------------
__global__ void k_reduce(const float* __restrict__ x) {
    __shared__ float ap[8][NJ];
    __shared__ float a_s[NJ];

    const int b   = blockIdx.x;
    const int tid = threadIdx.x;
    const float* xb = x + (size_t)b * (NT * NC * NJ);

    const int jj  = tid & 31;
    const int grp = tid >> 5;
    if (jj < NJ) {
        float s = 0.f;
        for (int r = grp; r < NT * NC; r += 8)
            s += xb[r * NJ + jj];
        ap[grp][jj] = s;
    }
    __syncthreads();

    if (tid < NJ) {
        float s = 0.f;
        #pragma unroll
        for (int g = 0; g < 8; ++g) s += ap[g][tid];
        a_s[tid] = s * (1.0f / (NT * NC));
    }
    __syncthreads();

    if (tid < 32) {
        float val = 0.f;
        if (tid < NJ) {
            float ak  = a_s[tid];
            float acc = 0.f;
            #pragma unroll
            for (int j = 0; j < NJ; ++j) {
                float d = a_s[j] - ak;
                acc = fmaf(d, d, acc);
            }
            val = sqrtf(acc);
            g_buf[b * NJ + tid] = val;
        }
        unsigned bmin = (tid < NJ) ? __float_as_uint(val) : 0x7f800000u;
        unsigned bmax = (tid < NJ) ? __float_as_uint(val) : 0u;
        unsigned wmin = __reduce_min_sync(0xffffffffu, bmin);
        unsigned wmax = __reduce_max_sync(0xffffffffu, bmax);
        if (tid == 0) {
            atomicMin(&g_min_bits, wmin);
            atomicMax(&g_max_bits, wmax);
        }
    }
}

// ---------------------------------------------------------------------------
// Kernel 2: Dm[i,k] = sqrt(max(||h_i - h_k||^2, 1e-12)), h normalized on the fly
// ---------------------------------------------------------------------------
__global__ void k_dist() {
    __shared__ float A[128][26];
    __shared__ float Bm[128][26];

    const int tid = threadIdx.x;
    const int r0  = blockIdx.y * 128;
    const int c0  = blockIdx.x * 128;

    const float lo  = __uint_as_float(g_min_bits);
    const float hi  = __uint_as_float(g_max_bits);
    const float rng = hi - lo;
    const float inv = (rng > 1e-8f) ? (1.0f / rng) : 0.0f;

    for (int i = tid; i < 128 * NJ; i += 256) {
        int r = i / NJ, j = i - r * NJ;
        A[r][j]  = (g_buf[(r0 + r) * NJ + j] - lo) * inv;
        Bm[r][j] = (g_buf[(c0 + r) * NJ + j] - lo) * inv;
    }
    __syncthreads();

    const int tx = tid & 15;
    const int ty = tid >> 4;

    float acc[8][8];
    #pragma unroll
    for (int i = 0; i < 8; ++i)
        #pragma unroll
        for (int k = 0; k < 8; ++k) acc[i][k] = 0.f;

    #pragma unroll
    for (int j = 0; j < NJ; ++j) {
        float ra[8], rb[8];
        #pragma unroll
        for (int i = 0; i < 8; ++i) {
            ra[i] = A[ty + 16 * i][j];
            rb[i] = Bm[tx + 16 * i][j];
        }
        #pragma unroll
        for (int i = 0; i < 8; ++i)
            #pragma unroll
            for (int k = 0; k < 8; ++k) {
                float d = ra[i] - rb[k];
                acc[i][k] = fmaf(d, d, acc[i][k]);
            }
    }

    #pragma unroll
    for (int i = 0; i < 8; ++i) {
        int rr = r0 + ty + 16 * i;
        #pragma unroll
        for (int k = 0; k < 8; ++k) {
            int cc = c0 + tx + 16 * k;
            Dm_buf[(size_t)rr * NB + cc] = sqrtf(fmaxf(acc[i][k], 1e-12f));
        }
    }
}

// ---------------------------------------------------------------------------
// Grid-wide sense-reversing barrier (all GRID_BVK blocks co-resident).
// ---------------------------------------------------------------------------
__device__ __forceinline__ void grid_barrier() {
    __syncthreads();
    if (threadIdx.x == 0) {
        __threadfence();
        unsigned gen = bar_gen;
        if (atomicAdd(&bar_count, 1u) == (unsigned)(gridDim.x - 1)) {
            bar_count = 0;
            __threadfence();
            bar_gen = gen + 1;
        } else {
            while (bar_gen == gen) { }
        }
        __threadfence();
    }
    __syncthreads();
}

// ---------------------------------------------------------------------------
// Kernel 3: persistent Boruvka; Dm slices live in SMEM for the whole kernel.
// key = (w_bits<<22) | (i<<11) | j   (w >= 0 so uint order == float order)
// 2 grid barriers per round; per-block redundant flatten into smem comp_s.
// ---------------------------------------------------------------------------
__global__ void __launch_bounds__(THR_BVK, 1)
k_boruvka() {
    extern __shared__ char smem_raw[];
    float* dm_s   = (float*)smem_raw;                      // [32][1024]
    int*   comp_s = (int*)(smem_raw + 32 * 1024 * 4);      // [2048]

    const int tid  = threadIdx.x;
    const int lane = tid & 31;
    const int w    = tid >> 5;
    const int gw   = blockIdx.x * 32 + w;   // 0..4095
    const int i    = gw >> 1;               // point handled by this warp
    const int part = gw & 1;                // which half of the row
    const unsigned long long KMAX = 0xFFFFFFFFFFFFFFFFull;

    // one-time: stage this warp's Dm half-row into smem
    float4* dm4 = (float4*)(dm_s + w * 1024);
    {
        const float4* src = (const float4*)(Dm_buf + (size_t)i * NB + part * 1024);
        #pragma unroll
        for (int k = 0; k < 8; ++k)
            dm4[k * 32 + lane] = src[k * 32 + lane];
    }

    const unsigned long long ibits = (unsigned long long)i << 11;
    const int jbase = part * 1024;

    for (int r = 0; r < ROUNDS; ++r) {
        const int nc = n_comp;              // consistent: read after barrier
        if (nc == 1) break;

        // ---- per-block flatten: parent_arr -> comp_s (roots) ----
        for (int v = tid; v < NB; v += THR_BVK) comp_s[v] = parent_arr[v];
        __syncthreads();
        for (int v = tid; v < NB; v += THR_BVK) {
            int p = comp_s[v];
            int q = comp_s[p];
            while (q != p) { p = q; q = comp_s[p]; }  // benign race: monotone
            comp_s[v] = p;
        }
        __syncthreads();

        // ---- phase A: min cross-component edge, smem-resident scan ----
        const int ci = comp_s[i];
        unsigned long long best = KMAX;
        const int4* cp4 = (const int4*)comp_s;
        #pragma unroll
        for (int k = 0; k < 8; ++k) {
            const int v = k * 32 + lane;
            float4 w4 = dm4[v];
            int4   c4 = cp4[part * 256 + v];
            const int jb = jbase + v * 4;
            if (c4.x != ci) {
                unsigned long long key = ((unsigned long long)__float_as_uint(w4.x) << 22) | ibits | (jb + 0);
                if (key < best) best = key;
            }
            if (c4.y != ci) {
                unsigned long long key = ((unsigned long long)__float_as_uint(w4.y) << 22) | ibits | (jb + 1);
                if (key < best) best = key;
            }
            if (c4.z != ci) {
                unsigned long long key = ((unsigned long long)__float_as_uint(w4.z) << 22) | ibits | (jb + 2);
                if (key < best) best = key;
            }
            if (c4.w != ci) {
                unsigned long long key = ((unsigned long long)__float_as_uint(w4.w) << 22) | ibits | (jb + 3);
                if (key < best) best = key;
            }
        }
        #pragma unroll
        for (int off = 16; off; off >>= 1) {
            unsigned long long o = __shfl_down_sync(0xffffffffu, best, off);
            if (o < best) best = o;
        }
        if (lane == 0 && best != KMAX)
            atomicMin(&best_r[r][ci], best);
        grid_barrier();

        // ---- phase B: hook roots + path-compress everyone ----
        {
            const int tg = blockIdx.x * THR_BVK + tid;
            if (tg < NB) {
                const int root = comp_s[tg];
                if (root == tg) {
                    unsigned long long b = best_r[r][tg];
                    if (b != KMAX) {
                        const int j  = (int)(b & 2047u);
                        const int rj = comp_s[j];
                        unsigned long long b2 = best_r[r][rj];
                        int back = (b2 != KMAX) ? comp_s[(int)(b2 & 2047u)] : -1;
                        const bool skip = (back == tg) && (tg > rj);
                        if (!skip) {
                            parent_arr[tg] = rj;
                            deaths_g[tg]   = __uint_as_float((unsigned)(b >> 22));
                            atomicSub((int*)&n_comp, 1);
                        }
                    }
                } else {
                    parent_arr[tg] = root;   // keep chains shallow
                }
            }
        }
        grid_barrier();
    }
}

// ---------------------------------------------------------------------------
// Kernel 4: StructureElementLayer over deaths (deterministic fixed-order sum).
// grid 32 x 256: each block computes 2 structure elements.
// ---------------------------------------------------------------------------
__global__ void __launch_bounds__(256, 1)
k_post(const float* __restrict__ centres,
       const float* __restrict__ sharp,
       float* __restrict__ out) {
    __shared__ float red[256];

    const int tid = threadIdx.x;
    const int sub = tid >> 7;               // 0/1 -> which element
    const int pl  = tid & 127;
    const int e   = blockIdx.x * 2 + sub;

    const float cx = centres[2 * e],  cy = centres[2 * e + 1];
    const float sx = sharp[2 * e],    sy = sharp[2 * e + 1];
    const float t0  = sx * sx * cx * cx;
    const float s2y = sy * sy;

    float acc = 0.f;
    for (int c = pl; c < NB; c += 128) {
        float d = deaths_g[c];
        if (d >= 0.f) {
            float dd = d - cy;
            acc += expf(-(t0 + s2y * dd * dd));
        }
    }
    red[tid] = acc;
    __syncthreads();
    #pragma unroll
    for (int s = 64; s; s >>= 1) {
        if (pl < s) red[sub * 128 + pl] += red[sub * 128 + pl + s];
        __syncthreads();
    }
    if (pl == 0) out[e] = red[sub * 128];
}

// ---------------------------------------------------------------------------
extern "C" void kernel_launch(void* const* d_in, const int* in_sizes, int n_in,
                              void* d_out, int out_size) {
    const float* x       = (const float*)d_in[0];
    const float* centres = (const float*)d_in[1];
    const float* sharp   = (const float*)d_in[2];
    float*       out     = (float*)d_out;

    static int smem_set = 0;
    if (!smem_set) {
        cudaFuncSetAttribute(k_boruvka,
                             cudaFuncAttributeMaxDynamicSharedMemorySize,
                             SMEM_BVK);
        smem_set = 1;
    }

    k_init<<<96, 256>>>();
    k_reduce<<<NB, 256>>>(x);
    k_dist<<<dim3(16, 16), 256>>>();
    k_boruvka<<<GRID_BVK, THR_BVK, SMEM_BVK>>>();
    k_post<<<32, 256>>>(centres, sharp, out);
}

// round 8
// speedup vs baseline: 17.2399x; 1.1868x over previous
#include <cuda_runtime.h>
#include <cuda_bf16.h>
#include <math.h>

// Problem constants
#define NB   2048      // batch -> number of points
#define NT   128
#define NC   3
#define NJ   25
#define NE   64

#define GRID_BVK   128          // 4096 warps = 2048 points x 2 half-rows
#define THR_BVK    1024
#define ROUNDS     12           // >= ceil(log2(2048)) + safety

// smem: dm 128KB + comp 8KB + parent 8KB + deaths 8KB
#define SMEM_BVK   (32 * 1024 * 4 + NB * 4 * 3)

// Scratch in device globals (no runtime allocation allowed)
__device__ float    g_buf[NB * NJ];
__device__ float    Dm_buf[(size_t)NB * NB];       // 16 MB distance matrix
__device__ unsigned g_min_bits;
__device__ unsigned g_max_bits;

// Boruvka cross-block state: ONLY the per-round best-edge buffers + barrier
__device__ unsigned long long best_r[ROUNDS][NB];  // fresh buffer per round
__device__ unsigned          bar_count;
__device__ volatile unsigned bar_gen;

// ---------------------------------------------------------------------------
__global__ void k_init() {
    if (threadIdx.x == 0) {
        g_min_bits = 0x7f800000u;
        g_max_bits = 0u;
        bar_count  = 0;
        bar_gen    = 0;
    }
}

// ---------------------------------------------------------------------------
// Kernel 1: a[b,j] = mean_{t,c} x[b,t,c,j];  g[b,k] = sqrt(sum_j (a_j-a_k)^2)
// ---------------------------------------------------------------------------
__global__ void k_reduce(const float* __restrict__ x) {
    __shared__ float ap[8][NJ];
    __shared__ float a_s[NJ];

    const int b   = blockIdx.x;
    const int tid = threadIdx.x;
    const float* xb = x + (size_t)b * (NT * NC * NJ);

    const int jj  = tid & 31;
    const int grp = tid >> 5;
    if (jj < NJ) {
        float s = 0.f;
        for (int r = grp; r < NT * NC; r += 8)
            s += xb[r * NJ + jj];
        ap[grp][jj] = s;
    }
    __syncthreads();

    if (tid < NJ) {
        float s = 0.f;
        #pragma unroll
        for (int g = 0; g < 8; ++g) s += ap[g][tid];
        a_s[tid] = s * (1.0f / (NT * NC));
    }
    __syncthreads();

    if (tid < 32) {
        float val = 0.f;
        if (tid < NJ) {
            float ak  = a_s[tid];
            float acc = 0.f;
            #pragma unroll
            for (int j = 0; j < NJ; ++j) {
                float d = a_s[j] - ak;
                acc = fmaf(d, d, acc);
            }
            val = sqrtf(acc);
            g_buf[b * NJ + tid] = val;
        }
        unsigned bmin = (tid < NJ) ? __float_as_uint(val) : 0x7f800000u;
        unsigned bmax = (tid < NJ) ? __float_as_uint(val) : 0u;
        unsigned wmin = __reduce_min_sync(0xffffffffu, bmin);
        unsigned wmax = __reduce_max_sync(0xffffffffu, bmax);
        if (tid == 0) {
            atomicMin(&g_min_bits, wmin);
            atomicMax(&g_max_bits, wmax);
        }
    }
}

// ---------------------------------------------------------------------------
// Kernel 2: Dm[i,k] = sqrt(max(||h_i - h_k||^2, 1e-12)), h normalized on the fly
// ---------------------------------------------------------------------------
__global__ void k_dist() {
    __shared__ float A[128][26];
    __shared__ float Bm[128][26];

    const int tid = threadIdx.x;
    const int r0  = blockIdx.y * 128;
    const int c0  = blockIdx.x * 128;

    const float lo  = __uint_as_float(g_min_bits);
    const float hi  = __uint_as_float(g_max_bits);
    const float rng = hi - lo;
    const float inv = (rng > 1e-8f) ? (1.0f / rng) : 0.0f;

    for (int i = tid; i < 128 * NJ; i += 256) {
        int r = i / NJ, j = i - r * NJ;
        A[r][j]  = (g_buf[(r0 + r) * NJ + j] - lo) * inv;
        Bm[r][j] = (g_buf[(c0 + r) * NJ + j] - lo) * inv;
    }
    __syncthreads();

    const int tx = tid & 15;
    const int ty = tid >> 4;

    float acc[8][8];
    #pragma unroll
    for (int i = 0; i < 8; ++i)
        #pragma unroll
        for (int k = 0; k < 8; ++k) acc[i][k] = 0.f;

    #pragma unroll
    for (int j = 0; j < NJ; ++j) {
        float ra[8], rb[8];
        #pragma unroll
        for (int i = 0; i < 8; ++i) {
            ra[i] = A[ty + 16 * i][j];
            rb[i] = Bm[tx + 16 * i][j];
        }
        #pragma unroll
        for (int i = 0; i < 8; ++i)
            #pragma unroll
            for (int k = 0; k < 8; ++k) {
                float d = ra[i] - rb[k];
                acc[i][k] = fmaf(d, d, acc[i][k]);
            }
    }

    #pragma unroll
    for (int i = 0; i < 8; ++i) {
        int rr = r0 + ty + 16 * i;
        #pragma unroll
        for (int k = 0; k < 8; ++k) {
            int cc = c0 + tx + 16 * k;
            Dm_buf[(size_t)rr * NB + cc] = sqrtf(fmaxf(acc[i][k], 1e-12f));
        }
    }
}

// ---------------------------------------------------------------------------
// Grid-wide sense-reversing barrier (all GRID_BVK blocks co-resident).
// ---------------------------------------------------------------------------
__device__ __forceinline__ void grid_barrier() {
    __syncthreads();
    if (threadIdx.x == 0) {
        __threadfence();
        unsigned gen = bar_gen;
        if (atomicAdd(&bar_count, 1u) == (unsigned)(gridDim.x - 1)) {
            bar_count = 0;
            __threadfence();
            bar_gen = gen + 1;
        } else {
            while (bar_gen == gen) { }
        }
        __threadfence();
    }
    __syncthreads();
}

// ---------------------------------------------------------------------------
// Kernel 3: persistent Boruvka, Dm slices SMEM-resident, ONE grid barrier per
// round. Hooking + flattening done redundantly per block in SMEM (identical
// inputs -> identical state in every block). Fused structure-layer epilogue.
// key = (w_bits<<22) | (i<<11) | j   (w >= 0 so uint order == float order)
// ---------------------------------------------------------------------------
__global__ void __launch_bounds__(THR_BVK, 1)
k_boruvka(const float* __restrict__ centres,
          const float* __restrict__ sharp,
          float* __restrict__ out) {
    extern __shared__ char smem_raw[];
    float* dm_s     = (float*)smem_raw;                        // [32][1024]
    int*   comp_s   = (int*)(smem_raw + 32 * 1024 * 4);        // [2048]
    int*   parent_s = (int*)(smem_raw + 32 * 1024 * 4 + NB*4); // [2048]
    float* deaths_s = (float*)(smem_raw + 32 * 1024 * 4 + NB*8);// [2048]
    __shared__ int hooks_sh;

    const int tid  = threadIdx.x;
    const int lane = tid & 31;
    const int w    = tid >> 5;
    const int gw   = blockIdx.x * 32 + w;   // 0..4095
    const int i    = gw >> 1;               // point handled by this warp
    const int part = gw & 1;                // which half of the row
    const unsigned long long KMAX = 0xFFFFFFFFFFFFFFFFull;

    // ---- init: local state + this block's slice of best_r ----
    for (int v = tid; v < NB; v += THR_BVK) {
        comp_s[v]   = v;
        parent_s[v] = v;
        deaths_s[v] = -1.0f;
    }
    {
        unsigned long long* br = (unsigned long long*)best_r;
        const int total = ROUNDS * NB;            // 24576
        const int per   = total / GRID_BVK;       // 192
        const int base  = blockIdx.x * per;
        for (int v = tid; v < per; v += THR_BVK)
            br[base + v] = KMAX;
    }

    // one-time: stage this warp's Dm half-row into smem
    float4* dm4 = (float4*)(dm_s + w * 1024);
    {
        const float4* src = (const float4*)(Dm_buf + (size_t)i * NB + part * 1024);
        #pragma unroll
        for (int k = 0; k < 8; ++k)
            dm4[k * 32 + lane] = src[k * 32 + lane];
    }
    grid_barrier();   // best_r init visible everywhere

    const unsigned long long ibits = (unsigned long long)i << 11;
    const int jbase = part * 1024;
    int nc = NB;

    for (int r = 0; r < ROUNDS; ++r) {
        if (nc == 1) break;   // nc identical in all blocks -> uniform

        // ---- phase A: min cross-component edge, smem-resident scan ----
        const int ci = comp_s[i];
        unsigned long long best = KMAX;
        const int4* cp4 = (const int4*)comp_s;
        #pragma unroll
        for (int k = 0; k < 8; ++k) {
            const int v = k * 32 + lane;
            float4 w4 = dm4[v];
            int4   c4 = cp4[part * 256 + v];
            const int jb = jbase + v * 4;
            if (c4.x != ci) {
                unsigned long long key = ((unsigned long long)__float_as_uint(w4.x) << 22) | ibits | (jb + 0);
                if (key < best) best = key;
            }
            if (c4.y != ci) {
                unsigned long long key = ((unsigned long long)__float_as_uint(w4.y) << 22) | ibits | (jb + 1);
                if (key < best) best = key;
            }
            if (c4.z != ci) {
                unsigned long long key = ((unsigned long long)__float_as_uint(w4.z) << 22) | ibits | (jb + 2);
                if (key < best) best = key;
            }
            if (c4.w != ci) {
                unsigned long long key = ((unsigned long long)__float_as_uint(w4.w) << 22) | ibits | (jb + 3);
                if (key < best) best = key;
            }
        }
        #pragma unroll
        for (int off = 16; off; off >>= 1) {
            unsigned long long o = __shfl_down_sync(0xffffffffu, best, off);
            if (o < best) best = o;
        }
        if (lane == 0 && best != KMAX)
            atomicMin(&best_r[r][ci], best);

        if (tid == 0) hooks_sh = 0;
        grid_barrier();   // all atomicMin for round r complete

        // ---- phase B (block-local, redundant): hook roots ----
        for (int c = tid; c < NB; c += THR_BVK) {
            if (comp_s[c] == c) {
                unsigned long long b = best_r[r][c];
                if (b != KMAX) {
                    const int j  = (int)(b & 2047u);
                    const int rj = comp_s[j];
                    unsigned long long b2 = best_r[r][rj];
                    int back = (b2 != KMAX) ? comp_s[(int)(b2 & 2047u)] : -1;
                    const bool skip = (back == c) && (c > rj);
                    if (!skip) {
                        parent_s[c] = rj;
                        deaths_s[c] = __uint_as_float((unsigned)(b >> 22));
                        atomicAdd(&hooks_sh, 1);
                    }
                }
            }
        }
        __syncthreads();

        // ---- phase C (block-local): flatten labels ----
        for (int v = tid; v < NB; v += THR_BVK) {
            int p = comp_s[v];
            int q = parent_s[p];
            while (q != p) { p = q; q = parent_s[p]; }
            comp_s[v] = p;
        }
        nc -= hooks_sh;
        __syncthreads();
    }

    // ---- fused StructureElementLayer epilogue ----
    // every block holds the full deaths_s; blocks 0..63 each emit one element
    if (blockIdx.x < NE) {
        const int e  = blockIdx.x;
        const float cx = centres[2 * e],  cy = centres[2 * e + 1];
        const float sx = sharp[2 * e],    sy = sharp[2 * e + 1];
        const float t0  = sx * sx * cx * cx;
        const float s2y = sy * sy;

        float acc = 0.f;
        #pragma unroll
        for (int k = 0; k < 2; ++k) {
            float d = deaths_s[tid + k * THR_BVK];
            if (d >= 0.f) {
                float dd = d - cy;
                acc += expf(-(t0 + s2y * dd * dd));
            }
        }
        // deterministic tree reduction (reuse comp_s region as float scratch)
        float* red = (float*)comp_s;
        red[tid] = acc;
        __syncthreads();
        #pragma unroll
        for (int s = 512; s; s >>= 1) {
            if (tid < s) red[tid] += red[tid + s];
            __syncthreads();
        }
        if (tid == 0) out[e] = red[0];
    }
}

// ---------------------------------------------------------------------------
extern "C" void kernel_launch(void* const* d_in, const int* in_sizes, int n_in,
                              void* d_out, int out_size) {
    const float* x       = (const float*)d_in[0];
    const float* centres = (const float*)d_in[1];
    const float* sharp   = (const float*)d_in[2];
    float*       out     = (float*)d_out;

    static int smem_set = 0;
    if (!smem_set) {
        cudaFuncSetAttribute(k_boruvka,
                             cudaFuncAttributeMaxDynamicSharedMemorySize,
                             SMEM_BVK);
        smem_set = 1;
    }

    k_init<<<1, 32>>>();
    k_reduce<<<NB, 256>>>(x);
    k_dist<<<dim3(16, 16), 256>>>();
    k_boruvka<<<GRID_BVK, THR_BVK, SMEM_BVK>>>(centres, sharp, out);
}